// round 2
// baseline (speedup 1.0000x reference)
#include <cuda_runtime.h>
#include <stdint.h>

// Problem shape (fixed by the dataset)
#define M_DIM 1024
#define K_DIM 2048
#define N_DIM 2048

// Tiling
#define BM 128
#define BN 64
#define KT 64
#define SA_STRIDE (KT + 4)   // 68 bytes: pad so staging/broadcast loads are conflict-free
#define SW_STRIDE (KT + 4)

#define SMEM_BYTES (65536 + BM * SA_STRIDE + BN * SW_STRIDE)  // 78592

// Scratch: quantized codes (allocation-free __device__ globals)
__device__ uint8_t g_A8[M_DIM * K_DIM];
__device__ uint8_t g_W8[N_DIM * K_DIM];

static __device__ __forceinline__ uint8_t clamp_u8(float v) {
    int c = (int)v;
    c = c < 0 ? 0 : (c > 255 ? 255 : c);
    return (uint8_t)c;
}

__global__ void quantA_kernel(const float* __restrict__ src) {
    int i = blockIdx.x * blockDim.x + threadIdx.x;   // index over groups of 4
    if (i < M_DIM * K_DIM / 4) {
        float4 v = ((const float4*)src)[i];
        uchar4 b;
        b.x = clamp_u8(v.x); b.y = clamp_u8(v.y);
        b.z = clamp_u8(v.z); b.w = clamp_u8(v.w);
        ((uchar4*)g_A8)[i] = b;
    }
}

__global__ void quantW_kernel(const float* __restrict__ src) {
    int i = blockIdx.x * blockDim.x + threadIdx.x;
    if (i < N_DIM * K_DIM / 4) {
        float4 v = ((const float4*)src)[i];
        uchar4 b;
        b.x = clamp_u8(v.x); b.y = clamp_u8(v.y);
        b.z = clamp_u8(v.z); b.w = clamp_u8(v.w);
        ((uchar4*)g_W8)[i] = b;
    }
}

// Main LUT-GEMM kernel.
// Grid: (N/BN, M/BM). Block: 256 threads = 8 warps (4 m-groups x 2 n-groups).
// Each warp: 32 m-rows x 32 n-lanes, 32 int accumulators per thread.
// a-code is warp-uniform (broadcast LDS), w-code is per-lane -> gather bank
// pattern is (w>>2)%32, ~4-way expected conflict.
__global__ void __launch_bounds__(256, 2)
lut_gemm_kernel(const int* __restrict__ lut,
                const float* __restrict__ bias,
                float* __restrict__ out) {
    extern __shared__ uint8_t smem[];
    uint8_t* sLUT = smem;                         // 65536 B
    uint8_t* sA   = smem + 65536;                 // BM * SA_STRIDE
    uint8_t* sW   = sA + BM * SA_STRIDE;          // BN * SW_STRIDE

    const int tid  = threadIdx.x;
    const int lane = tid & 31;
    const int warp = tid >> 5;
    const int wm   = warp & 3;   // 4 m-groups
    const int wn   = warp >> 2;  // 2 n-groups

    // Load LUT (int32 -> uint8) into shared, once.
    for (int i = tid; i < 65536 / 4; i += 256) {
        int4 v = ((const int4*)lut)[i];
        uchar4 b;
        b.x = (uint8_t)v.x; b.y = (uint8_t)v.y;
        b.z = (uint8_t)v.z; b.w = (uint8_t)v.w;
        ((uchar4*)sLUT)[i] = b;
    }

    const int m0 = blockIdx.y * BM;
    const int n0 = blockIdx.x * BN;

    const int mBase = wm * 32;             // this warp's first row within tile
    const int nLane = n0 + wn * 32 + lane; // this lane's output column

    int acc[32];
#pragma unroll
    for (int i = 0; i < 32; i++) acc[i] = 0;

    const uint8_t* gA = g_A8 + (size_t)m0 * K_DIM;
    const uint8_t* gW = g_W8 + (size_t)n0 * K_DIM;

    const uint8_t* sWrow = sW + (wn * 32 + lane) * SW_STRIDE;
    const uint8_t* sArow = sA + mBase * SA_STRIDE;

    for (int k0 = 0; k0 < K_DIM; k0 += KT) {
        __syncthreads();  // previous-tile reads done (also orders LUT stores on iter 0)

        // Stage A tile: BM rows x KT bytes (as u32 words)
        for (int i = tid; i < BM * (KT / 4); i += 256) {
            int m  = i >> 4;       // / (KT/4)
            int kw = i & 15;
            uint32_t v = *(const uint32_t*)(gA + (size_t)m * K_DIM + k0 + kw * 4);
            *(uint32_t*)(sA + m * SA_STRIDE + kw * 4) = v;
        }
        // Stage W tile: BN rows x KT bytes
        for (int i = tid; i < BN * (KT / 4); i += 256) {
            int nn = i >> 4;
            int kw = i & 15;
            uint32_t v = *(const uint32_t*)(gW + (size_t)nn * K_DIM + k0 + kw * 4);
            *(uint32_t*)(sW + nn * SW_STRIDE + kw * 4) = v;
        }
        __syncthreads();

#pragma unroll 1
        for (int kk = 0; kk < KT; kk += 4) {
            // per-lane w codes for 4 consecutive k
            uint32_t wword = *(const uint32_t*)(sWrow + kk);
            uint32_t w0 =  wword        & 255u;
            uint32_t w1 = (wword >> 8)  & 255u;
            uint32_t w2 = (wword >> 16) & 255u;
            uint32_t w3 = (wword >> 24);

#pragma unroll
            for (int m = 0; m < 32; m++) {
                // warp-uniform a codes for 4 consecutive k (broadcast load)
                uint32_t aword = *(const uint32_t*)(sArow + m * SA_STRIDE + kk);
                // idx = a*256 + w built as ((aword>>s)&0xFF00) | w  -> SHF + LOP3
                uint32_t i0 = ((aword << 8)  & 0xFF00u) | w0;
                uint32_t i1 = ( aword        & 0xFF00u) | w1;
                uint32_t i2 = ((aword >> 8)  & 0xFF00u) | w2;
                uint32_t i3 = ((aword >> 16) & 0xFF00u) | w3;
                acc[m] += sLUT[i0];
                acc[m] += sLUT[i1];
                acc[m] += sLUT[i2];
                acc[m] += sLUT[i3];
            }
        }
    }

    const float b = bias[nLane];
#pragma unroll
    for (int m = 0; m < 32; m++) {
        out[(size_t)(m0 + mBase + m) * N_DIM + nLane] = (float)acc[m] + b;
    }
}

extern "C" void kernel_launch(void* const* d_in, const int* in_sizes, int n_in,
                              void* d_out, int out_size) {
    const float* input  = (const float*)d_in[0];  // [M, K] codes as f32
    const float* weight = (const float*)d_in[1];  // [N, K] codes as f32
    const float* bias   = (const float*)d_in[2];  // [N]
    const int*   lut    = (const int*)d_in[3];    // [256*256]
    float* out = (float*)d_out;

    (void)in_sizes; (void)n_in; (void)out_size;

    // Opt-in to >48KB dynamic smem (idempotent; not a stream op, capture-safe)
    cudaFuncSetAttribute((const void*)lut_gemm_kernel,
                         cudaFuncAttributeMaxDynamicSharedMemorySize, SMEM_BYTES);

    quantA_kernel<<<(M_DIM * K_DIM / 4 + 255) / 256, 256>>>(input);
    quantW_kernel<<<(N_DIM * K_DIM / 4 + 255) / 256, 256>>>(weight);

    dim3 grid(N_DIM / BN, M_DIM / BM);  // (32, 8)
    lut_gemm_kernel<<<grid, 256, SMEM_BYTES>>>(lut, bias, out);
}

// round 3
// speedup vs baseline: 1.1757x; 1.1757x over previous
#include <cuda_runtime.h>
#include <stdint.h>

// Problem shape (fixed by the dataset)
#define M_DIM 1024
#define K_DIM 2048
#define N_DIM 2048

// Tiling: 64 x 32 output tile per CTA, 128 threads (4 warps).
// Each warp: 16 m-rows x 32 n-lanes, acc[16] per thread.
#define BM 64
#define BN 32
#define KT 64
#define SA_STRIDE 72   // 64 + 8 pad, 8B-aligned rows for LDS.64
#define SW_STRIDE 72

#define SMEM_BYTES (65536 + BM * SA_STRIDE + BN * SW_STRIDE)  // 72448

// Scratch: quantized codes (allocation-free __device__ globals)
__device__ uint8_t g_A8[M_DIM * K_DIM];
__device__ uint8_t g_W8[N_DIM * K_DIM];
__device__ uint8_t g_LUT8[65536];

static __device__ __forceinline__ uint8_t clamp_u8(float v) {
    int c = (int)v;
    c = c < 0 ? 0 : (c > 255 ? 255 : c);
    return (uint8_t)c;
}

__global__ void quantA_kernel(const float* __restrict__ src) {
    int i = blockIdx.x * blockDim.x + threadIdx.x;   // groups of 4
    if (i < M_DIM * K_DIM / 4) {
        float4 v = ((const float4*)src)[i];
        uchar4 b;
        b.x = clamp_u8(v.x); b.y = clamp_u8(v.y);
        b.z = clamp_u8(v.z); b.w = clamp_u8(v.w);
        ((uchar4*)g_A8)[i] = b;
    }
}

__global__ void quantW_kernel(const float* __restrict__ src) {
    int i = blockIdx.x * blockDim.x + threadIdx.x;
    if (i < N_DIM * K_DIM / 4) {
        float4 v = ((const float4*)src)[i];
        uchar4 b;
        b.x = clamp_u8(v.x); b.y = clamp_u8(v.y);
        b.z = clamp_u8(v.z); b.w = clamp_u8(v.w);
        ((uchar4*)g_W8)[i] = b;
    }
}

__global__ void quantLUT_kernel(const int* __restrict__ lut) {
    int i = blockIdx.x * blockDim.x + threadIdx.x;   // groups of 4
    if (i < 65536 / 4) {
        int4 v = ((const int4*)lut)[i];
        uchar4 b;
        b.x = (uint8_t)v.x; b.y = (uint8_t)v.y;
        b.z = (uint8_t)v.z; b.w = (uint8_t)v.w;
        ((uchar4*)g_LUT8)[i] = b;
    }
}

// Main LUT-GEMM kernel.
// Grid: 1024 CTAs (16 m-tiles x 64 n-tiles), block 128 threads, occ 3.
// 1024 tiles over 148 SMs -> per-SM tile count 6.92 avg, <=7 with the
// hardware's wave work-stealing -> ~1.2% imbalance (vs 15.7% before).
__global__ void __launch_bounds__(128, 3)
lut_gemm_kernel(const float* __restrict__ bias,
                float* __restrict__ out) {
    extern __shared__ uint8_t smem[];
    uint8_t* sLUT = smem;                         // 65536 B
    uint8_t* sA   = smem + 65536;                 // BM * SA_STRIDE
    uint8_t* sW   = sA + BM * SA_STRIDE;          // BN * SW_STRIDE

    const int tid  = threadIdx.x;
    const int lane = tid & 31;
    const int warp = tid >> 5;   // 0..3 -> m-group

    // Copy pre-quantized LUT (64KB) into shared with 16B vector loads.
    for (int i = tid; i < 65536 / 16; i += 128) {
        ((uint4*)sLUT)[i] = ((const uint4*)g_LUT8)[i];
    }

    const int tileId = blockIdx.x;
    const int m0 = (tileId >> 6) * BM;   // 16 tile rows
    const int n0 = (tileId & 63) * BN;   // 64 tile cols

    const int mBase = warp * 16;         // warp's first row within tile
    const int nLane = n0 + lane;         // this lane's output column

    int acc[16];
#pragma unroll
    for (int i = 0; i < 16; i++) acc[i] = 0;

    const uint8_t* gA = g_A8 + (size_t)m0 * K_DIM;
    const uint8_t* gW = g_W8 + (size_t)n0 * K_DIM;

    const uint8_t* sWrow = sW + lane * SW_STRIDE;
    const uint8_t* sArow = sA + mBase * SA_STRIDE;

    for (int k0 = 0; k0 < K_DIM; k0 += KT) {
        __syncthreads();  // previous-tile reads done (also orders LUT copy on iter 0)

        // Stage A tile: BM rows x KT bytes (u32 words). 1024 words / 128 thr.
        for (int i = tid; i < BM * (KT / 4); i += 128) {
            int m  = i >> 4;       // / (KT/4)
            int kw = i & 15;
            uint32_t v = *(const uint32_t*)(gA + (size_t)m * K_DIM + k0 + kw * 4);
            *(uint32_t*)(sA + m * SA_STRIDE + kw * 4) = v;
        }
        // Stage W tile: BN rows x KT bytes. 512 words / 128 thr.
        for (int i = tid; i < BN * (KT / 4); i += 128) {
            int nn = i >> 4;
            int kw = i & 15;
            uint32_t v = *(const uint32_t*)(gW + (size_t)nn * K_DIM + k0 + kw * 4);
            *(uint32_t*)(sW + nn * SW_STRIDE + kw * 4) = v;
        }
        __syncthreads();

#pragma unroll 1
        for (int kk = 0; kk < KT; kk += 8) {
            // per-lane w codes for 8 consecutive k (one LDS.64)
            uint32_t wlo = ((const uint2*)(sWrow + kk))->x;
            uint32_t whi = ((const uint2*)(sWrow + kk))->y;
            uint32_t w0 =  wlo        & 255u;
            uint32_t w1 = (wlo >> 8)  & 255u;
            uint32_t w2 = (wlo >> 16) & 255u;
            uint32_t w3 =  wlo >> 24;
            uint32_t w4 =  whi        & 255u;
            uint32_t w5 = (whi >> 8)  & 255u;
            uint32_t w6 = (whi >> 16) & 255u;
            uint32_t w7 =  whi >> 24;

#pragma unroll
            for (int m = 0; m < 16; m++) {
                // warp-uniform a codes for 8 consecutive k (broadcast LDS.64)
                uint2 av = *(const uint2*)(sArow + m * SA_STRIDE + kk);
                uint32_t alo = av.x, ahi = av.y;
                // idx = a*256 + w built as ((aword shift)&0xFF00)|w -> SHF+LOP3
                uint32_t i0 = ((alo << 8)  & 0xFF00u) | w0;
                uint32_t i1 = ( alo        & 0xFF00u) | w1;
                uint32_t i2 = ((alo >> 8)  & 0xFF00u) | w2;
                uint32_t i3 = ((alo >> 16) & 0xFF00u) | w3;
                uint32_t i4 = ((ahi << 8)  & 0xFF00u) | w4;
                uint32_t i5 = ( ahi        & 0xFF00u) | w5;
                uint32_t i6 = ((ahi >> 8)  & 0xFF00u) | w6;
                uint32_t i7 = ((ahi >> 16) & 0xFF00u) | w7;
                acc[m] += sLUT[i0];
                acc[m] += sLUT[i1];
                acc[m] += sLUT[i2];
                acc[m] += sLUT[i3];
                acc[m] += sLUT[i4];
                acc[m] += sLUT[i5];
                acc[m] += sLUT[i6];
                acc[m] += sLUT[i7];
            }
        }
    }

    const float b = bias[nLane];
#pragma unroll
    for (int m = 0; m < 16; m++) {
        out[(size_t)(m0 + mBase + m) * N_DIM + nLane] = (float)acc[m] + b;
    }
}

extern "C" void kernel_launch(void* const* d_in, const int* in_sizes, int n_in,
                              void* d_out, int out_size) {
    const float* input  = (const float*)d_in[0];  // [M, K] codes as f32
    const float* weight = (const float*)d_in[1];  // [N, K] codes as f32
    const float* bias   = (const float*)d_in[2];  // [N]
    const int*   lut    = (const int*)d_in[3];    // [256*256]
    float* out = (float*)d_out;

    (void)in_sizes; (void)n_in; (void)out_size;

    // Opt-in to >48KB dynamic smem (idempotent; capture-safe)
    cudaFuncSetAttribute((const void*)lut_gemm_kernel,
                         cudaFuncAttributeMaxDynamicSharedMemorySize, SMEM_BYTES);

    quantA_kernel<<<(M_DIM * K_DIM / 4 + 255) / 256, 256>>>(input);
    quantW_kernel<<<(N_DIM * K_DIM / 4 + 255) / 256, 256>>>(weight);
    quantLUT_kernel<<<(65536 / 4 + 255) / 256, 256>>>(lut);

    dim3 grid(1024);  // 16 x 64 tiles of 64 x 32
    lut_gemm_kernel<<<grid, 128, SMEM_BYTES>>>(bias, out);
}